// round 14
// baseline (speedup 1.0000x reference)
#include <cuda_runtime.h>
#include <cstdint>

// UpsampleNearest4D: x (2,8,8,16,64,64) f32, x2 on axes 2..5.
// Output (2,8,16,32,128,128).
//
// R14: R5 structure (input-driven, one thread per input float2, eight
// independent STG.128 {a,a,b,b}), but stores are st.global.wt
// (write-through) — the only L2 write policy not yet tested. Each warp
// store is 512B contiguous (full 32B sectors), so write-through cannot
// fragment into partial-sector writes. Tests whether the ~72% DRAM
// plateau includes an L2 dirty-line bookkeeping stage.

__global__ __launch_bounds__(512) void upsample4d_kernel(
    const float2* __restrict__ in, float4* __restrict__ out)
{
    unsigned idx = blockIdx.x * 512u + threadIdx.x;   // [0, 4194304)

    unsigned x2 = idx & 31u;            // float2 column within input row
    unsigned r  = idx >> 5;
    unsigned y  = r & 63u;  r >>= 6;
    unsigned z  = r & 15u;  r >>= 4;
    unsigned t  = r & 7u;   r >>= 3;
    unsigned nc = r;                    // [0,16)

    float2 v = __ldg(&in[idx]);
    float4 o = make_float4(v.x, v.x, v.y, v.y);

    // Output strides in float4 units: row = 128/4 = 32
    const unsigned SY = 32u;                 // one output row (512B)
    const unsigned SZ = 128u * 32u;          // OY rows
    const unsigned ST = 32u * 128u * 32u;    // OZ * OY rows

    unsigned base = ((((nc * 16u + 2u * t) * 32u + 2u * z) * 128u + 2u * y) * 32u) + x2;

    float4* p0 = out + base;
    float4* p1 = out + base + ST;

    #define STWT(ptr) asm volatile( \
        "st.global.wt.v4.f32 [%0], {%1,%2,%3,%4};" \
        :: "l"(ptr), "f"(o.x), "f"(o.y), "f"(o.z), "f"(o.w) : "memory")

    STWT(p0);
    STWT(p0 + SY);
    STWT(p0 + SZ);
    STWT(p0 + SZ + SY);
    STWT(p1);
    STWT(p1 + SY);
    STWT(p1 + SZ);
    STWT(p1 + SZ + SY);

    #undef STWT
}

extern "C" void kernel_launch(void* const* d_in, const int* in_sizes, int n_in,
                              void* d_out, int out_size)
{
    const float2* in = (const float2*)d_in[0];
    float4* out = (float4*)d_out;

    // 8,388,608 input floats -> 4,194,304 float2 threads
    const unsigned n_threads = 8u * 1024u * 1024u / 2u;
    upsample4d_kernel<<<n_threads / 512u, 512u>>>(in, out);
}